// round 2
// baseline (speedup 1.0000x reference)
#include <cuda_runtime.h>
#include <cuda_bf16.h>

typedef unsigned long long u64;

// ---- packed f32x2 helpers (sm_100a; ptxas never emits FFMA2 from C++) ----
__device__ __forceinline__ u64 pack2_dup(float v) {
    u64 r; asm("mov.b64 %0, {%1, %1};" : "=l"(r) : "f"(v)); return r;
}
__device__ __forceinline__ u64 pack2(float lo, float hi) {
    u64 r; asm("mov.b64 %0, {%1, %2};" : "=l"(r) : "f"(lo), "f"(hi)); return r;
}
__device__ __forceinline__ void fma2(u64 &d, u64 a, u64 b) {
    asm("fma.rn.f32x2 %0, %1, %2, %0;" : "+l"(d) : "l"(a), "l"(b));
}
__device__ __forceinline__ void unpack2(u64 v, float &lo, float &hi) {
    asm("mov.b64 {%0, %1}, %2;" : "=f"(lo), "=f"(hi) : "l"(v));
}

// ---- problem geometry ----
// x: [4,20,20,40,40,8]  k: [3,3,3,3,8,16]  out: [4,18,18,38,38,16], VALID, stride 1
constexpr int Tt = 20, Zz = 20, Hh = 40, Ww = 40, CI = 8;
constexpr int Bb = 4;
constexpr int OT = 18, OZ = 18, OH = 38, OW = 38, CO = 16;
constexpr int HP = OH / 2, WP = OW / 2;              // 19 x 19 2x2-point tiles
constexpr int NWORK = Bb * OT * OZ * HP * WP;        // 467,856 threads
// x strides (floats)
constexpr int XS_H = Ww * CI;                        // 320
constexpr int XS_Z = Hh * XS_H;                      // 12,800
constexpr int XS_T = Zz * XS_Z;                      // 256,000
constexpr int XS_B = Tt * XS_T;                      // 5,120,000
constexpr int NWGT = 81 * CI * CO;                   // 10,368 floats = 41.5 KB

__global__ void __launch_bounds__(256, 1) conv4d_kernel(
    const float* __restrict__ x, const float* __restrict__ wgt,
    const float* __restrict__ bias, float* __restrict__ out)
{
    // Full weight tensor in SMEM, original [tap][ci][co] layout.
    __shared__ __align__(16) float sw[NWGT];
    {
        const float4* g4 = (const float4*)wgt;
        float4* s4 = (float4*)sw;
        for (int i = threadIdx.x; i < NWGT / 4; i += 256) s4[i] = g4[i];
    }
    __syncthreads();

    int idx = blockIdx.x * 256 + threadIdx.x;
    const bool active = idx < NWORK;
    int id = active ? idx : 0;     // inactive threads compute garbage in-bounds, skip store
    int wp = id % WP; id /= WP;
    int hp = id % HP; id /= HP;
    int z  = id % OZ; id /= OZ;
    int t  = id % OT;
    int b  = id / OT;
    const int h0 = hp * 2, w0 = wp * 2;

    // 2x2 output points x 16 couts as 8 f32x2 accumulators each, bias-initialized.
    u64 acc[4][8];
    #pragma unroll
    for (int cp = 0; cp < 8; cp++) {
        u64 bv = pack2(bias[cp * 2], bias[cp * 2 + 1]);
        #pragma unroll
        for (int p = 0; p < 4; p++) acc[p][cp] = bv;
    }

    const float* xb = x + b * XS_B + t * XS_T + z * XS_Z + h0 * XS_H + w0 * CI;

    #pragma unroll 1
    for (int kt = 0; kt < 3; kt++) {
        #pragma unroll 1
        for (int kz = 0; kz < 3; kz++) {
            #pragma unroll 1
            for (int kh = 0; kh < 3; kh++) {
                const float* xh  = xb + kt * XS_T + kz * XS_Z + kh * XS_H;
                const float* swb = sw + ((kt * 3 + kz) * 3 + kh) * 3 * (CI * CO);
                #pragma unroll
                for (int kw = 0; kw < 3; kw++) {
                    // Stage 2 rows x 16 contiguous floats (2 W-points x 8 ci each).
                    const float* xp = xh + kw * CI;
                    float xr[2][16];
                    #pragma unroll
                    for (int ph = 0; ph < 2; ph++) {
                        #pragma unroll
                        for (int i = 0; i < 4; i++) {
                            float4 v = *(const float4*)(xp + ph * XS_H + i * 4);
                            xr[ph][i * 4 + 0] = v.x; xr[ph][i * 4 + 1] = v.y;
                            xr[ph][i * 4 + 2] = v.z; xr[ph][i * 4 + 3] = v.w;
                        }
                    }
                    const float* swt = swb + kw * (CI * CO);
                    #pragma unroll
                    for (int ci = 0; ci < 8; ci++) {
                        // 16 couts for this (tap, ci): 4 uniform LDS.128 -> 8 f32x2 pairs
                        const float4* wq = (const float4*)(swt + ci * CO);
                        float4 f0 = wq[0];
                        float4 f1 = wq[1];
                        float4 f2 = wq[2];
                        float4 f3 = wq[3];
                        u64 w01 = pack2(f0.x, f0.y), w23 = pack2(f0.z, f0.w);
                        u64 w45 = pack2(f1.x, f1.y), w67 = pack2(f1.z, f1.w);
                        u64 w89 = pack2(f2.x, f2.y), wAB = pack2(f2.z, f2.w);
                        u64 wCD = pack2(f3.x, f3.y), wEF = pack2(f3.z, f3.w);
                        #pragma unroll
                        for (int ph = 0; ph < 2; ph++) {
                            #pragma unroll
                            for (int pw = 0; pw < 2; pw++) {
                                const int p = ph * 2 + pw;
                                u64 xx = pack2_dup(xr[ph][pw * 8 + ci]);
                                fma2(acc[p][0], xx, w01);
                                fma2(acc[p][1], xx, w23);
                                fma2(acc[p][2], xx, w45);
                                fma2(acc[p][3], xx, w67);
                                fma2(acc[p][4], xx, w89);
                                fma2(acc[p][5], xx, wAB);
                                fma2(acc[p][6], xx, wCD);
                                fma2(acc[p][7], xx, wEF);
                            }
                        }
                    }
                }
            }
        }
    }

    if (active) {
        #pragma unroll
        for (int ph = 0; ph < 2; ph++) {
            #pragma unroll
            for (int pw = 0; pw < 2; pw++) {
                const int p = ph * 2 + pw;
                float* o = out + (((((b * OT + t) * OZ + z) * OH + (h0 + ph)) * OW
                                   + (w0 + pw)) * CO);
                #pragma unroll
                for (int cp = 0; cp < 8; cp += 2) {
                    float4 v;
                    unpack2(acc[p][cp],     v.x, v.y);
                    unpack2(acc[p][cp + 1], v.z, v.w);
                    *(float4*)(o + cp * 2) = v;
                }
            }
        }
    }
}

extern "C" void kernel_launch(void* const* d_in, const int* in_sizes, int n_in,
                              void* d_out, int out_size)
{
    const float* x    = (const float*)d_in[0];
    const float* wgt  = (const float*)d_in[1];
    const float* bias = (const float*)d_in[2];
    float* out        = (float*)d_out;
    const int blocks = (NWORK + 255) / 256;
    conv4d_kernel<<<blocks, 256>>>(x, wgt, bias, out);
}

// round 5
// speedup vs baseline: 1.0758x; 1.0758x over previous
#include <cuda_runtime.h>
#include <cuda_bf16.h>

typedef unsigned long long u64;

// ---- packed f32x2 helpers (sm_100a; ptxas never emits FFMA2 from C++) ----
__device__ __forceinline__ u64 pack2_dup(float v) {
    u64 r; asm("mov.b64 %0, {%1, %1};" : "=l"(r) : "f"(v)); return r;
}
__device__ __forceinline__ u64 pack2(float lo, float hi) {
    u64 r; asm("mov.b64 %0, {%1, %2};" : "=l"(r) : "f"(lo), "f"(hi)); return r;
}
__device__ __forceinline__ void fma2(u64 &d, u64 a, u64 b) {
    asm("fma.rn.f32x2 %0, %1, %2, %0;" : "+l"(d) : "l"(a), "l"(b));
}
__device__ __forceinline__ void unpack2(u64 v, float &lo, float &hi) {
    asm("mov.b64 {%0, %1}, %2;" : "=f"(lo), "=f"(hi) : "l"(v));
}

// ---- problem geometry ----
// x: [4,20,20,40,40,8]  k: [3,3,3,3,8,16]  out: [4,18,18,38,38,16], VALID, stride 1
constexpr int Tt = 20, Zz = 20, Hh = 40, Ww = 40, CI = 8;
constexpr int Bb = 4;
constexpr int OT = 18, OZ = 18, OH = 38, OW = 38, CO = 16;
constexpr int HP = OH / 2, WP = OW / 2;              // 19 x 19 2x2-point tiles
constexpr int NWORK = Bb * OT * OZ * HP * WP;        // 467,856 threads
// x strides (floats)
constexpr int XS_H = Ww * CI;                        // 320
constexpr int XS_Z = Hh * XS_H;                      // 12,800
constexpr int XS_T = Zz * XS_Z;                      // 256,000
constexpr int XS_B = Tt * XS_T;                      // 5,120,000
constexpr int NWGT = 81 * CI * CO;                   // 10,368 floats = 41.5 KB

constexpr int TPB = 128;                             // 3 CTAs/SM -> 12 warps

__global__ void __launch_bounds__(TPB, 3) conv4d_kernel(
    const float* __restrict__ x, const float* __restrict__ wgt,
    const float* __restrict__ bias, float* __restrict__ out)
{
    // Full weight tensor in SMEM, original [tap][ci][co] layout.
    // 16 B at (tap, ci) = couts {0..3} pairs -> read directly as 2x f32x2.
    __shared__ __align__(16) float sw[NWGT];
    {
        const float4* g4 = (const float4*)wgt;
        float4* s4 = (float4*)sw;
        for (int i = threadIdx.x; i < NWGT / 4; i += TPB) s4[i] = g4[i];
    }
    __syncthreads();

    int idx = blockIdx.x * TPB + threadIdx.x;
    const bool active = idx < NWORK;
    int id = active ? idx : 0;     // inactive threads compute garbage in-bounds, skip store
    int wp = id % WP; id /= WP;
    int hp = id % HP; id /= HP;
    int z  = id % OZ; id /= OZ;
    int t  = id % OT;
    int b  = id / OT;
    const int h0 = hp * 2, w0 = wp * 2;

    // 2x2 output points x 16 couts as 8 f32x2 accumulators each, bias-initialized.
    u64 acc[4][8];
    #pragma unroll
    for (int cp = 0; cp < 8; cp++) {
        u64 bv = pack2(bias[cp * 2], bias[cp * 2 + 1]);
        #pragma unroll
        for (int p = 0; p < 4; p++) acc[p][cp] = bv;
    }

    const float* xb = x + b * XS_B + t * XS_T + z * XS_Z + h0 * XS_H + w0 * CI;

    #pragma unroll 1
    for (int kt = 0; kt < 3; kt++) {
        #pragma unroll 1
        for (int kz = 0; kz < 3; kz++) {
            #pragma unroll 1
            for (int kh = 0; kh < 3; kh++) {
                const float* xh  = xb + kt * XS_T + kz * XS_Z + kh * XS_H;
                const float* swb = sw + ((kt * 3 + kz) * 3 + kh) * 3 * (CI * CO);

                // Hoisted x staging: union of ci-blocks needed by kw 0..2 and
                // pw 0..1 is blocks w0..w0+3 = 32 consecutive floats per row.
                float xr[2][32];
                #pragma unroll
                for (int ph = 0; ph < 2; ph++) {
                    #pragma unroll
                    for (int i = 0; i < 8; i++) {
                        float4 v = *(const float4*)(xh + ph * XS_H + i * 4);
                        xr[ph][i * 4 + 0] = v.x; xr[ph][i * 4 + 1] = v.y;
                        xr[ph][i * 4 + 2] = v.z; xr[ph][i * 4 + 3] = v.w;
                    }
                }

                #pragma unroll
                for (int kw = 0; kw < 3; kw++) {
                    const float* swt = swb + kw * (CI * CO);
                    #pragma unroll
                    for (int ci = 0; ci < 8; ci++) {
                        // 16 couts for this (tap, ci): 4 uniform broadcast
                        // LDS.128 -> 8 f32x2 operands, no repacking.
                        const ulonglong2* wq = (const ulonglong2*)(swt + ci * CO);
                        ulonglong2 q0 = wq[0];
                        ulonglong2 q1 = wq[1];
                        ulonglong2 q2 = wq[2];
                        ulonglong2 q3 = wq[3];
                        #pragma unroll
                        for (int ph = 0; ph < 2; ph++) {
                            #pragma unroll
                            for (int pw = 0; pw < 2; pw++) {
                                const int p = ph * 2 + pw;
                                u64 xx = pack2_dup(xr[ph][(kw + pw) * 8 + ci]);
                                fma2(acc[p][0], xx, q0.x);
                                fma2(acc[p][1], xx, q0.y);
                                fma2(acc[p][2], xx, q1.x);
                                fma2(acc[p][3], xx, q1.y);
                                fma2(acc[p][4], xx, q2.x);
                                fma2(acc[p][5], xx, q2.y);
                                fma2(acc[p][6], xx, q3.x);
                                fma2(acc[p][7], xx, q3.y);
                            }
                        }
                    }
                }
            }
        }
    }

    if (active) {
        #pragma unroll
        for (int ph = 0; ph < 2; ph++) {
            #pragma unroll
            for (int pw = 0; pw < 2; pw++) {
                const int p = ph * 2 + pw;
                float* o = out + (((((b * OT + t) * OZ + z) * OH + (h0 + ph)) * OW
                                   + (w0 + pw)) * CO);
                #pragma unroll
                for (int cp = 0; cp < 8; cp += 2) {
                    float4 v;
                    unpack2(acc[p][cp],     v.x, v.y);
                    unpack2(acc[p][cp + 1], v.z, v.w);
                    *(float4*)(o + cp * 2) = v;
                }
            }
        }
    }
}

extern "C" void kernel_launch(void* const* d_in, const int* in_sizes, int n_in,
                              void* d_out, int out_size)
{
    const float* x    = (const float*)d_in[0];
    const float* wgt  = (const float*)d_in[1];
    const float* bias = (const float*)d_in[2];
    float* out        = (float*)d_out;
    const int blocks = (NWORK + TPB - 1) / TPB;
    conv4d_kernel<<<blocks, TPB>>>(x, wgt, bias, out);
}